// round 11
// baseline (speedup 1.0000x reference)
#include <cuda_runtime.h>
#include <cuda_fp16.h>
#include <cstdint>

#define VOCAB   50257
#define VPAD    50304        /* 393 * 128 */
#define NEMBD   768
#define NROWS   8192
#define SEQLEN  1024
#define NSPLIT  9
#define NCHUNK  12           /* 768 / 64 */

#define SMEM_A_OFF 0
#define SMEM_B_OFF (NCHUNK * 16384)             /* 196608 */
#define SMEM_BYTES (SMEM_B_OFF + 2 * 16384)     /* 229376 */

// ---------------- device scratch ----------------
__device__ __align__(256) __half g_X[(size_t)NROWS * NEMBD];   // fp16(gelu(wte+wpe))
__device__ __align__(256) __half g_W[(size_t)VPAD * NEMBD];    // fp16(W), zero-padded
__device__ float g_pmax[NSPLIT][4][NROWS];    // per (split, wn-quarter)
__device__ float g_psum[NSPLIT][4][NROWS];
__device__ float g_ll[NROWS];
__device__ float g_row[NROWS];

// ---------------- helpers ----------------
__device__ __forceinline__ uint32_t smem_u32(const void* p) {
    uint32_t a;
    asm("{ .reg .u64 t; cvta.to.shared.u64 t, %1; cvt.u32.u64 %0, t; }" : "=r"(a) : "l"(p));
    return a;
}
__device__ __forceinline__ void cp_async16(uint32_t dst, const void* src) {
    asm volatile("cp.async.cg.shared.global [%0], [%1], 16;" :: "r"(dst), "l"(src));
}
__device__ __forceinline__ void cp_commit() {
    asm volatile("cp.async.commit_group;" ::: "memory");
}
template <int N>
__device__ __forceinline__ void cp_wait() {
    asm volatile("cp.async.wait_group %0;" :: "n"(N) : "memory");
}
__device__ __forceinline__ void ldsm_x4(uint32_t (&r)[4], uint32_t addr) {
    asm volatile("ldmatrix.sync.aligned.m8n8.x4.shared.b16 {%0,%1,%2,%3}, [%4];"
                 : "=r"(r[0]), "=r"(r[1]), "=r"(r[2]), "=r"(r[3]) : "r"(addr));
}
// fp16 in, fp16 accumulate; D/C are 2x f16x2 regs
__device__ __forceinline__ void mma16816_f16(uint32_t* c, const uint32_t* a, const uint32_t* b) {
    asm volatile(
        "mma.sync.aligned.m16n8k16.row.col.f16.f16.f16.f16 "
        "{%0,%1}, {%2,%3,%4,%5}, {%6,%7}, {%0,%1};"
        : "+r"(c[0]), "+r"(c[1])
        : "r"(a[0]), "r"(a[1]), "r"(a[2]), "r"(a[3]), "r"(b[0]), "r"(b[1]));
}
__device__ __forceinline__ uint32_t swz(uint32_t bo) { return bo ^ ((bo >> 3) & 0x70u); }

// ---------------- kernel: x = fp16(gelu(wte[tok] + wpe[pos])) ----------------
__global__ void prep_x_kernel(const int* __restrict__ data, const float* __restrict__ wte,
                              const float* __restrict__ wpe) {
    int idx = blockIdx.x * blockDim.x + threadIdx.x;
    if (idx >= NROWS * (NEMBD / 4)) return;
    int row = idx / (NEMBD / 4);
    int c4  = idx % (NEMBD / 4);
    int tok = data[row];
    int pos = row & (SEQLEN - 1);
    float4 a = *reinterpret_cast<const float4*>(wte + (size_t)tok * NEMBD + c4 * 4);
    float4 p = *reinterpret_cast<const float4*>(wpe + (size_t)pos * NEMBD + c4 * 4);
    const float K0 = 0.7978845608028654f, K1 = 0.044715f;
    float v[4] = {a.x + p.x, a.y + p.y, a.z + p.z, a.w + p.w};
    float g[4];
#pragma unroll
    for (int i = 0; i < 4; i++) {
        float x = v[i];
        g[i] = 0.5f * x * (1.0f + tanhf(K0 * (x + K1 * x * x * x)));
    }
    __half2* dst = reinterpret_cast<__half2*>(&g_X[(size_t)row * NEMBD + c4 * 4]);
    dst[0] = __floats2half2_rn(g[0], g[1]);
    dst[1] = __floats2half2_rn(g[2], g[3]);
}

// ---------------- kernel: W fp32 -> fp16 (zero-padded rows) ----------------
__global__ void conv_w_kernel(const float* __restrict__ W) {
    int idx = blockIdx.x * blockDim.x + threadIdx.x;
    if (idx >= VPAD * (NEMBD / 4)) return;
    int v  = idx / (NEMBD / 4);
    int c4 = idx % (NEMBD / 4);
    __half2 r0, r1;
    if (v < VOCAB) {
        float4 w = *reinterpret_cast<const float4*>(W + (size_t)v * NEMBD + c4 * 4);
        r0 = __floats2half2_rn(w.x, w.y);
        r1 = __floats2half2_rn(w.z, w.w);
    } else {
        r0 = __floats2half2_rn(0.f, 0.f);
        r1 = r0;
    }
    __half2* dst = reinterpret_cast<__half2*>(&g_W[(size_t)v * NEMBD + c4 * 4]);
    dst[0] = r0;
    dst[1] = r1;
}

// ---------------- kernel: label logits from the SAME fp16 operands ----------------
__global__ void label_logit_kernel(const int* __restrict__ label) {
    int wid = threadIdx.x >> 5, lid = threadIdx.x & 31;
    int row = blockIdx.x * 8 + wid;
    int lab = label[row];
    const __half2* xr = reinterpret_cast<const __half2*>(&g_X[(size_t)row * NEMBD]);
    const __half2* wr = reinterpret_cast<const __half2*>(&g_W[(size_t)lab * NEMBD]);
    float acc = 0.f;
#pragma unroll
    for (int it = 0; it < 12; it++) {
        __half2 x2 = xr[it * 32 + lid];
        __half2 w2 = wr[it * 32 + lid];
        acc += __low2float(x2) * __low2float(w2) + __high2float(x2) * __high2float(w2);
    }
#pragma unroll
    for (int o = 16; o; o >>= 1) acc += __shfl_xor_sync(0xFFFFFFFFu, acc, o);
    if (lid == 0) g_ll[row] = acc;
}

// ---------------- fused GEMM (fp16 mma, fp16 accum) + online logsumexp ----------------
// 512 threads = 16 warps (4M x 4N); warp tile 32x32; CTA tile 128x128 (same as R6).
// 4 warps/SMSP for latency hiding; chunk structure, barrier count, smem layout,
// and cp.async pattern identical to the best (R6) kernel.
__global__ void __launch_bounds__(512, 1)
gemm_lse_kernel() {
    extern __shared__ char smem[];
    const uint32_t smem_base = smem_u32(smem);
    const int tid  = threadIdx.x;
    const int lane = tid & 31;
    const int wid  = tid >> 5;
    const int wm   = wid >> 2;          // 0..3
    const int wn   = wid & 3;           // 0..3
    const int s    = blockIdx.x;
    const int m0   = blockIdx.y * 128;

    // ---- cp.async mapping (512 threads, 128 rows x 128B per chunk: 2 lines/thread) ----
    const int rb  = tid >> 3;           // 0..63
    const int seg = tid & 7;            // 0..7
    const uint32_t cpo  = swz((uint32_t)rb * 128u + (uint32_t)seg * 16u);
    const uint32_t cpo1 = swz((uint32_t)(rb + 64) * 128u + (uint32_t)seg * 16u);

    // ---- resident A: 12 chunks of 128x64 fp16 (one group) ----
#pragma unroll 1
    for (int kk = 0; kk < NCHUNK; kk++) {
        uint32_t abase = smem_base + SMEM_A_OFF + kk * 16384;
        const __half* src = &g_X[(size_t)(m0 + rb) * NEMBD + kk * 64 + seg * 8];
        cp_async16(abase + cpo,  src);
        cp_async16(abase + cpo1, src + 64 * NEMBD);
    }
    cp_commit();

    // vocab tile range: 393 = 6*44 + 3*43
    const int t0   = s * 43 + (s < 6 ? s : 6);
    const int tcnt = 43 + (s < 6 ? 1 : 0);
    const int NC   = tcnt * NCHUNK;

    // ---- B chunk 0 into buf0 ----
    {
        uint32_t bbase = smem_base + SMEM_B_OFF;
        const __half* src = &g_W[(size_t)(t0 * 128 + rb) * NEMBD + seg * 8];
        cp_async16(bbase + cpo,  src);
        cp_async16(bbase + cpo1, src + 64 * NEMBD);
    }
    cp_commit();

    // ---- ldmatrix lane constants ----
    const int quad = lane >> 3;
    const int lrow = lane & 7;
    const int a_row = wm * 32 + (quad & 1) * 8 + lrow;    // + mi*16
    const int a_c8  = (quad >> 1);
    const int b_row = wn * 32 + (quad >> 1) * 8 + lrow;   // + p*16
    const int b_c8  = (quad & 1);

    float m_run[4], s_run[4];
#pragma unroll
    for (int i = 0; i < 4; i++) { m_run[i] = -3.0e38f; s_run[i] = 0.0f; }

    uint32_t c[2][4][2];   // [mi][nj][2 f16x2]
#pragma unroll
    for (int mi = 0; mi < 2; mi++)
#pragma unroll
        for (int nj = 0; nj < 4; nj++) { c[mi][nj][0] = 0u; c[mi][nj][1] = 0u; }

    int v0 = t0 * 128;
    int kk = 0;
    int vp = t0 * 128;
    int kp = 1;

#pragma unroll 1
    for (int g = 0; g < NC; g++) {
        cp_wait<0>();
        __syncthreads();

        const uint32_t Ab = smem_base + SMEM_A_OFF + kk * 16384;
        const uint32_t Bb = smem_base + SMEM_B_OFF + (g & 1) * 16384;

        // ks = 0 LDSMs, then prefetch, then MMAs
        uint32_t a0[2][4], b0[2][4];
#pragma unroll
        for (int mi = 0; mi < 2; mi++) {
            uint32_t bo = (uint32_t)(a_row + mi * 16) * 128u + (uint32_t)(a_c8 * 8) * 2u;
            ldsm_x4(a0[mi], Ab + swz(bo));
        }
#pragma unroll
        for (int p = 0; p < 2; p++) {
            uint32_t bo = (uint32_t)(b_row + p * 16) * 128u + (uint32_t)(b_c8 * 8) * 2u;
            ldsm_x4(b0[p], Bb + swz(bo));
        }

        if (g + 1 < NC) {
            uint32_t bbase = smem_base + SMEM_B_OFF + ((g + 1) & 1) * 16384;
            const __half* src = &g_W[(size_t)(vp + rb) * NEMBD + kp * 64 + seg * 8];
            cp_async16(bbase + cpo,  src);
            cp_async16(bbase + cpo1, src + 64 * NEMBD);
        }
        cp_commit();
        kp++;
        if (kp == NCHUNK) { kp = 0; vp += 128; }

#pragma unroll
        for (int mi = 0; mi < 2; mi++)
#pragma unroll
            for (int p = 0; p < 2; p++) {
                mma16816_f16(c[mi][p * 2 + 0], a0[mi], &b0[p][0]);
                mma16816_f16(c[mi][p * 2 + 1], a0[mi], &b0[p][2]);
            }

#pragma unroll
        for (int ks = 1; ks < 4; ks++) {
            const int kc = ks * 16;
            uint32_t a[2][4], b[2][4];
#pragma unroll
            for (int mi = 0; mi < 2; mi++) {
                uint32_t bo = (uint32_t)(a_row + mi * 16) * 128u
                            + (uint32_t)(kc + a_c8 * 8) * 2u;
                ldsm_x4(a[mi], Ab + swz(bo));
            }
#pragma unroll
            for (int p = 0; p < 2; p++) {
                uint32_t bo = (uint32_t)(b_row + p * 16) * 128u
                            + (uint32_t)(kc + b_c8 * 8) * 2u;
                ldsm_x4(b[p], Bb + swz(bo));
            }
#pragma unroll
            for (int mi = 0; mi < 2; mi++)
#pragma unroll
                for (int p = 0; p < 2; p++) {
                    mma16816_f16(c[mi][p * 2 + 0], a[mi], &b[p][0]);
                    mma16816_f16(c[mi][p * 2 + 1], a[mi], &b[p][2]);
                }
        }

        kk++;
        if (kk == NCHUNK) {
            // ---- tile epilogue (overlaps in-flight prefetch) ----
            kk = 0;
            const bool edge = (v0 + 128 > VOCAB);
            const int colb = v0 + wn * 32 + 2 * (lane & 3);
#pragma unroll
            for (int sl = 0; sl < 4; sl++) {
                const int mi = sl >> 1, h = sl & 1;
                float vv[4][2];
#pragma unroll
                for (int nj = 0; nj < 4; nj++) {
                    float2 f = __half22float2(*reinterpret_cast<__half2*>(&c[mi][nj][h]));
                    vv[nj][0] = f.x; vv[nj][1] = f.y;
                }
                if (edge) {
#pragma unroll
                    for (int nj = 0; nj < 4; nj++)
#pragma unroll
                        for (int e = 0; e < 2; e++)
                            if (colb + nj * 8 + e >= VOCAB) vv[nj][e] = -3.0e38f;
                }
                float tm = -3.0e38f;
#pragma unroll
                for (int nj = 0; nj < 4; nj++) {
                    tm = fmaxf(tm, vv[nj][0]);
                    tm = fmaxf(tm, vv[nj][1]);
                }
                tm = fmaxf(tm, __shfl_xor_sync(0xFFFFFFFFu, tm, 1));
                tm = fmaxf(tm, __shfl_xor_sync(0xFFFFFFFFu, tm, 2));
                float nm = fmaxf(m_run[sl], tm);
                float p = 0.0f;
#pragma unroll
                for (int nj = 0; nj < 4; nj++) {
                    p += __expf(vv[nj][0] - nm);
                    p += __expf(vv[nj][1] - nm);
                }
                p += __shfl_xor_sync(0xFFFFFFFFu, p, 1);
                p += __shfl_xor_sync(0xFFFFFFFFu, p, 2);
                s_run[sl] = s_run[sl] * __expf(m_run[sl] - nm) + p;
                m_run[sl] = nm;
            }
            v0 += 128;
#pragma unroll
            for (int mi = 0; mi < 2; mi++)
#pragma unroll
                for (int nj = 0; nj < 4; nj++) { c[mi][nj][0] = 0u; c[mi][nj][1] = 0u; }
        }
    }

    // ---- store per-row partials keyed by (s, wn) ----
    if ((lane & 3) == 0) {
#pragma unroll
        for (int sl = 0; sl < 4; sl++) {
            const int mi = sl >> 1, h = sl & 1;
            int row = m0 + wm * 32 + mi * 16 + h * 8 + (lane >> 2);
            g_pmax[s][wn][row] = m_run[sl];
            g_psum[s][wn][row] = s_run[sl];
        }
    }
}

// ---------------- kernel: per-row NLL ----------------
__global__ void rownll_kernel() {
    int r = blockIdx.x * 256 + threadIdx.x;
    float m = g_pmax[0][0][r];
#pragma unroll
    for (int s = 0; s < NSPLIT; s++)
#pragma unroll
        for (int q = 0; q < 4; q++) m = fmaxf(m, g_pmax[s][q][r]);
    float S = 0.f;
#pragma unroll
    for (int s = 0; s < NSPLIT; s++)
#pragma unroll
        for (int q = 0; q < 4; q++) S += g_psum[s][q][r] * __expf(g_pmax[s][q][r] - m);
    g_row[r] = (m + logf(S)) - g_ll[r];
}

// ---------------- kernel: deterministic mean ----------------
__global__ void reduce_kernel(float* __restrict__ out) {
    __shared__ float red[256];
    int t = threadIdx.x;
    float local = 0.f;
#pragma unroll
    for (int i = 0; i < NROWS / 256; i++) local += g_row[t + i * 256];
    red[t] = local;
    __syncthreads();
    for (int off = 128; off; off >>= 1) {
        if (t < off) red[t] += red[t + off];
        __syncthreads();
    }
    if (t == 0) out[0] = red[0] * (1.0f / (float)NROWS);
}

// ---------------- launch (gemm kept 4th for ncu capture) ----------------
extern "C" void kernel_launch(void* const* d_in, const int* in_sizes, int n_in,
                              void* d_out, int out_size) {
    const int*   data  = (const int*)d_in[0];
    const int*   label = (const int*)d_in[1];
    const float* wte   = (const float*)d_in[2];
    const float* wpe   = (const float*)d_in[3];
    const float* W     = (const float*)d_in[4];
    float* out = (float*)d_out;

    cudaFuncSetAttribute(gemm_lse_kernel, cudaFuncAttributeMaxDynamicSharedMemorySize, SMEM_BYTES);

    prep_x_kernel<<<(NROWS * (NEMBD / 4)) / 256, 256>>>(data, wte, wpe);
    conv_w_kernel<<<(VPAD * (NEMBD / 4)) / 256, 256>>>(W);
    label_logit_kernel<<<NROWS / 8, 256>>>(label);
    gemm_lse_kernel<<<dim3(NSPLIT, NROWS / 128), 512, SMEM_BYTES>>>();
    rownll_kernel<<<NROWS / 256, 256>>>();
    reduce_kernel<<<1, 256>>>(out);
}

// round 12
// speedup vs baseline: 1.1993x; 1.1993x over previous
#include <cuda_runtime.h>
#include <cuda_fp16.h>
#include <cstdint>

#define VOCAB   50257
#define VPAD    50304        /* 393 * 128 */
#define NEMBD   768
#define NROWS   8192
#define SEQLEN  1024
#define NSPLIT  9
#define NCHUNK  12           /* 768 / 64 */

#define STAGE_BYTES 32768    /* A chunk 16KB + B chunk 16KB */
#define SMEM_BYTES  (3 * STAGE_BYTES)   /* 98304 -> 2 CTAs/SM */

// ---------------- device scratch ----------------
__device__ __align__(256) __half g_X[(size_t)NROWS * NEMBD];   // fp16(gelu(wte+wpe))
__device__ __align__(256) __half g_W[(size_t)VPAD * NEMBD];    // fp16(W), zero-padded
__device__ float g_pmax[NSPLIT][2][NROWS];
__device__ float g_psum[NSPLIT][2][NROWS];
__device__ float g_ll[NROWS];
__device__ float g_row[NROWS];

// ---------------- helpers ----------------
__device__ __forceinline__ uint32_t smem_u32(const void* p) {
    uint32_t a;
    asm("{ .reg .u64 t; cvta.to.shared.u64 t, %1; cvt.u32.u64 %0, t; }" : "=r"(a) : "l"(p));
    return a;
}
__device__ __forceinline__ void cp_async16(uint32_t dst, const void* src) {
    asm volatile("cp.async.cg.shared.global [%0], [%1], 16;" :: "r"(dst), "l"(src));
}
__device__ __forceinline__ void cp_commit() {
    asm volatile("cp.async.commit_group;" ::: "memory");
}
template <int N>
__device__ __forceinline__ void cp_wait() {
    asm volatile("cp.async.wait_group %0;" :: "n"(N) : "memory");
}
__device__ __forceinline__ void ldsm_x4(uint32_t (&r)[4], uint32_t addr) {
    asm volatile("ldmatrix.sync.aligned.m8n8.x4.shared.b16 {%0,%1,%2,%3}, [%4];"
                 : "=r"(r[0]), "=r"(r[1]), "=r"(r[2]), "=r"(r[3]) : "r"(addr));
}
// fp16 in, fp16 accumulate; D/C are 2x f16x2 regs
__device__ __forceinline__ void mma16816_f16(uint32_t* c, const uint32_t* a, const uint32_t* b) {
    asm volatile(
        "mma.sync.aligned.m16n8k16.row.col.f16.f16.f16.f16 "
        "{%0,%1}, {%2,%3,%4,%5}, {%6,%7}, {%0,%1};"
        : "+r"(c[0]), "+r"(c[1])
        : "r"(a[0]), "r"(a[1]), "r"(a[2]), "r"(a[3]), "r"(b[0]), "r"(b[1]));
}
__device__ __forceinline__ uint32_t swz(uint32_t bo) { return bo ^ ((bo >> 3) & 0x70u); }

// ---------------- kernel: x = fp16(gelu(wte[tok] + wpe[pos])) ----------------
__global__ void prep_x_kernel(const int* __restrict__ data, const float* __restrict__ wte,
                              const float* __restrict__ wpe) {
    int idx = blockIdx.x * blockDim.x + threadIdx.x;
    if (idx >= NROWS * (NEMBD / 4)) return;
    int row = idx / (NEMBD / 4);
    int c4  = idx % (NEMBD / 4);
    int tok = data[row];
    int pos = row & (SEQLEN - 1);
    float4 a = *reinterpret_cast<const float4*>(wte + (size_t)tok * NEMBD + c4 * 4);
    float4 p = *reinterpret_cast<const float4*>(wpe + (size_t)pos * NEMBD + c4 * 4);
    const float K0 = 0.7978845608028654f, K1 = 0.044715f;
    float v[4] = {a.x + p.x, a.y + p.y, a.z + p.z, a.w + p.w};
    float g[4];
#pragma unroll
    for (int i = 0; i < 4; i++) {
        float x = v[i];
        g[i] = 0.5f * x * (1.0f + tanhf(K0 * (x + K1 * x * x * x)));
    }
    __half2* dst = reinterpret_cast<__half2*>(&g_X[(size_t)row * NEMBD + c4 * 4]);
    dst[0] = __floats2half2_rn(g[0], g[1]);
    dst[1] = __floats2half2_rn(g[2], g[3]);
}

// ---------------- kernel: W fp32 -> fp16 (zero-padded rows) ----------------
__global__ void conv_w_kernel(const float* __restrict__ W) {
    int idx = blockIdx.x * blockDim.x + threadIdx.x;
    if (idx >= VPAD * (NEMBD / 4)) return;
    int v  = idx / (NEMBD / 4);
    int c4 = idx % (NEMBD / 4);
    __half2 r0, r1;
    if (v < VOCAB) {
        float4 w = *reinterpret_cast<const float4*>(W + (size_t)v * NEMBD + c4 * 4);
        r0 = __floats2half2_rn(w.x, w.y);
        r1 = __floats2half2_rn(w.z, w.w);
    } else {
        r0 = __floats2half2_rn(0.f, 0.f);
        r1 = r0;
    }
    __half2* dst = reinterpret_cast<__half2*>(&g_W[(size_t)v * NEMBD + c4 * 4]);
    dst[0] = r0;
    dst[1] = r1;
}

// ---------------- kernel: label logits from the SAME fp16 operands ----------------
__global__ void label_logit_kernel(const int* __restrict__ label) {
    int wid = threadIdx.x >> 5, lid = threadIdx.x & 31;
    int row = blockIdx.x * 8 + wid;
    int lab = label[row];
    const __half2* xr = reinterpret_cast<const __half2*>(&g_X[(size_t)row * NEMBD]);
    const __half2* wr = reinterpret_cast<const __half2*>(&g_W[(size_t)lab * NEMBD]);
    float acc = 0.f;
#pragma unroll
    for (int it = 0; it < 12; it++) {
        __half2 x2 = xr[it * 32 + lid];
        __half2 w2 = wr[it * 32 + lid];
        acc += __low2float(x2) * __low2float(w2) + __high2float(x2) * __high2float(w2);
    }
#pragma unroll
    for (int o = 16; o; o >>= 1) acc += __shfl_xor_sync(0xFFFFFFFFu, acc, o);
    if (lid == 0) g_ll[row] = acc;
}

// ---------------- fused GEMM (fp16 mma, fp16 accum) + online logsumexp ----------------
// 256 threads = 8 warps (4M x 2N); warp tile 32x64; CTA tile 128x128.
// BOTH A and B streamed via a 3-stage cp.async pipeline (stage = A 16KB + B 16KB),
// smem 96KB -> TWO independent CTAs per SM. Each CTA's barrier/epilogue bubbles are
// filled by the co-resident CTA's MMAs (independent barriers).
__global__ void __launch_bounds__(256, 2)
gemm_lse_kernel() {
    extern __shared__ char smem[];
    const uint32_t smem_base = smem_u32(smem);
    const int tid  = threadIdx.x;
    const int lane = tid & 31;
    const int wid  = tid >> 5;
    const int wm   = wid >> 1;
    const int wn   = wid & 1;
    const int s    = blockIdx.x;
    const int m0   = blockIdx.y * 128;

    const int rb  = tid >> 3;           // 0..31
    const int seg = tid & 7;            // 0..7
    const uint32_t cpo  = swz((uint32_t)rb * 128u + (uint32_t)seg * 16u);
    const uint32_t cpo1 = swz((uint32_t)(rb + 32) * 128u + (uint32_t)seg * 16u);
    const uint32_t cpo2 = swz((uint32_t)(rb + 64) * 128u + (uint32_t)seg * 16u);
    const uint32_t cpo3 = swz((uint32_t)(rb + 96) * 128u + (uint32_t)seg * 16u);

    // vocab tile range: 393 = 6*44 + 3*43
    const int t0   = s * 43 + (s < 6 ? s : 6);
    const int tcnt = 43 + (s < 6 ? 1 : 0);
    const int NC   = tcnt * NCHUNK;

    // A source rows fixed for this CTA
    const __half* aX = &g_X[(size_t)(m0 + rb) * NEMBD + seg * 8];

    // ---- prologue: stages 0 (chunk 0) and 1 (chunk 1), one group each ----
#pragma unroll
    for (int pre = 0; pre < 2; pre++) {
        uint32_t sa = smem_base + pre * STAGE_BYTES;
        uint32_t sb = sa + 16384;
        const __half* srcA = aX + pre * 64;
        const __half* srcB = &g_W[(size_t)(t0 * 128 + rb) * NEMBD + pre * 64 + seg * 8];
        cp_async16(sa + cpo,  srcA);
        cp_async16(sa + cpo1, srcA + 32 * NEMBD);
        cp_async16(sa + cpo2, srcA + 64 * NEMBD);
        cp_async16(sa + cpo3, srcA + 96 * NEMBD);
        cp_async16(sb + cpo,  srcB);
        cp_async16(sb + cpo1, srcB + 32 * NEMBD);
        cp_async16(sb + cpo2, srcB + 64 * NEMBD);
        cp_async16(sb + cpo3, srcB + 96 * NEMBD);
        cp_commit();
    }

    // ---- ldmatrix lane constants ----
    const int quad = lane >> 3;
    const int lrow = lane & 7;
    const int a_row = wm * 32 + (quad & 1) * 8 + lrow;
    const int a_c8  = (quad >> 1);
    const int b_row = wn * 64 + (quad >> 1) * 8 + lrow;
    const int b_c8  = (quad & 1);

    float m_run[4], s_run[4];
#pragma unroll
    for (int i = 0; i < 4; i++) { m_run[i] = -3.0e38f; s_run[i] = 0.0f; }

    uint32_t c[2][8][2];
#pragma unroll
    for (int mi = 0; mi < 2; mi++)
#pragma unroll
        for (int nj = 0; nj < 8; nj++) { c[mi][nj][0] = 0u; c[mi][nj][1] = 0u; }

    int v0 = t0 * 128;    // current tile vocab base
    int kk = 0;           // chunk within tile
    int vp = t0 * 128;    // prefetch tile vocab base (chunk g+2)
    int kp = 2;           // prefetch chunk-in-tile
    int st  = 0;          // compute stage
    int pst = 2;          // prefetch stage

#pragma unroll 1
    for (int g = 0; g < NC; g++) {
        cp_wait<1>();
        __syncthreads();

        const uint32_t Ab = smem_base + st * STAGE_BYTES;
        const uint32_t Bb = Ab + 16384;

        // ks = 0 LDSMs first (start loads), then prefetch, then MMAs
        uint32_t a0[2][4], b0[4][4];
#pragma unroll
        for (int mi = 0; mi < 2; mi++) {
            uint32_t bo = (uint32_t)(a_row + mi * 16) * 128u + (uint32_t)(a_c8 * 8) * 2u;
            ldsm_x4(a0[mi], Ab + swz(bo));
        }
#pragma unroll
        for (int p = 0; p < 4; p++) {
            uint32_t bo = (uint32_t)(b_row + p * 16) * 128u + (uint32_t)(b_c8 * 8) * 2u;
            ldsm_x4(b0[p], Bb + swz(bo));
        }

        // prefetch chunk g+2 into stage pst (read last at g-1; safe under the barrier)
        if (g + 2 < NC) {
            uint32_t sa = smem_base + pst * STAGE_BYTES;
            uint32_t sb = sa + 16384;
            const __half* srcA = aX + kp * 64;
            const __half* srcB = &g_W[(size_t)(vp + rb) * NEMBD + kp * 64 + seg * 8];
            cp_async16(sa + cpo,  srcA);
            cp_async16(sa + cpo1, srcA + 32 * NEMBD);
            cp_async16(sa + cpo2, srcA + 64 * NEMBD);
            cp_async16(sa + cpo3, srcA + 96 * NEMBD);
            cp_async16(sb + cpo,  srcB);
            cp_async16(sb + cpo1, srcB + 32 * NEMBD);
            cp_async16(sb + cpo2, srcB + 64 * NEMBD);
            cp_async16(sb + cpo3, srcB + 96 * NEMBD);
        }
        cp_commit();
        kp++;
        if (kp == NCHUNK) { kp = 0; vp += 128; }
        pst = (pst == 2) ? 0 : pst + 1;

#pragma unroll
        for (int mi = 0; mi < 2; mi++)
#pragma unroll
            for (int p = 0; p < 4; p++) {
                mma16816_f16(c[mi][p * 2 + 0], a0[mi], &b0[p][0]);
                mma16816_f16(c[mi][p * 2 + 1], a0[mi], &b0[p][2]);
            }

#pragma unroll
        for (int ks = 1; ks < 4; ks++) {
            const int kc = ks * 16;
            uint32_t a[2][4], b[4][4];
#pragma unroll
            for (int mi = 0; mi < 2; mi++) {
                uint32_t bo = (uint32_t)(a_row + mi * 16) * 128u
                            + (uint32_t)(kc + a_c8 * 8) * 2u;
                ldsm_x4(a[mi], Ab + swz(bo));
            }
#pragma unroll
            for (int p = 0; p < 4; p++) {
                uint32_t bo = (uint32_t)(b_row + p * 16) * 128u
                            + (uint32_t)(kc + b_c8 * 8) * 2u;
                ldsm_x4(b[p], Bb + swz(bo));
            }
#pragma unroll
            for (int mi = 0; mi < 2; mi++)
#pragma unroll
                for (int p = 0; p < 4; p++) {
                    mma16816_f16(c[mi][p * 2 + 0], a[mi], &b[p][0]);
                    mma16816_f16(c[mi][p * 2 + 1], a[mi], &b[p][2]);
                }
        }

        st = (st == 2) ? 0 : st + 1;

        kk++;
        if (kk == NCHUNK) {
            // ---- tile epilogue (registers only; co-resident CTA fills the pipe) ----
            kk = 0;
            const bool edge = (v0 + 128 > VOCAB);
            const int colb = v0 + wn * 64 + 2 * (lane & 3);
#pragma unroll
            for (int sl = 0; sl < 4; sl++) {
                const int mi = sl >> 1, h = sl & 1;
                float vv[8][2];
#pragma unroll
                for (int nj = 0; nj < 8; nj++) {
                    float2 f = __half22float2(*reinterpret_cast<__half2*>(&c[mi][nj][h]));
                    vv[nj][0] = f.x; vv[nj][1] = f.y;
                }
                if (edge) {
#pragma unroll
                    for (int nj = 0; nj < 8; nj++)
#pragma unroll
                        for (int e = 0; e < 2; e++)
                            if (colb + nj * 8 + e >= VOCAB) vv[nj][e] = -3.0e38f;
                }
                float tm = -3.0e38f;
#pragma unroll
                for (int nj = 0; nj < 8; nj++) {
                    tm = fmaxf(tm, vv[nj][0]);
                    tm = fmaxf(tm, vv[nj][1]);
                }
                tm = fmaxf(tm, __shfl_xor_sync(0xFFFFFFFFu, tm, 1));
                tm = fmaxf(tm, __shfl_xor_sync(0xFFFFFFFFu, tm, 2));
                float nm = fmaxf(m_run[sl], tm);
                float p = 0.0f;
#pragma unroll
                for (int nj = 0; nj < 8; nj++) {
                    p += __expf(vv[nj][0] - nm);
                    p += __expf(vv[nj][1] - nm);
                }
                p += __shfl_xor_sync(0xFFFFFFFFu, p, 1);
                p += __shfl_xor_sync(0xFFFFFFFFu, p, 2);
                s_run[sl] = s_run[sl] * __expf(m_run[sl] - nm) + p;
                m_run[sl] = nm;
            }
            v0 += 128;
#pragma unroll
            for (int mi = 0; mi < 2; mi++)
#pragma unroll
                for (int nj = 0; nj < 8; nj++) { c[mi][nj][0] = 0u; c[mi][nj][1] = 0u; }
        }
    }

    // ---- store per-row partials keyed by (s, wn) ----
    if ((lane & 3) == 0) {
#pragma unroll
        for (int sl = 0; sl < 4; sl++) {
            const int mi = sl >> 1, h = sl & 1;
            int row = m0 + wm * 32 + mi * 16 + h * 8 + (lane >> 2);
            g_pmax[s][wn][row] = m_run[sl];
            g_psum[s][wn][row] = s_run[sl];
        }
    }
}

// ---------------- kernel: per-row NLL ----------------
__global__ void rownll_kernel() {
    int r = blockIdx.x * 256 + threadIdx.x;
    float m = g_pmax[0][0][r];
#pragma unroll
    for (int s = 0; s < NSPLIT; s++) {
        m = fmaxf(m, g_pmax[s][0][r]);
        m = fmaxf(m, g_pmax[s][1][r]);
    }
    float S = 0.f;
#pragma unroll
    for (int s = 0; s < NSPLIT; s++) {
        S += g_psum[s][0][r] * __expf(g_pmax[s][0][r] - m);
        S += g_psum[s][1][r] * __expf(g_pmax[s][1][r] - m);
    }
    g_row[r] = (m + logf(S)) - g_ll[r];
}

// ---------------- kernel: deterministic mean ----------------
__global__ void reduce_kernel(float* __restrict__ out) {
    __shared__ float red[256];
    int t = threadIdx.x;
    float local = 0.f;
#pragma unroll
    for (int i = 0; i < NROWS / 256; i++) local += g_row[t + i * 256];
    red[t] = local;
    __syncthreads();
    for (int off = 128; off; off >>= 1) {
        if (t < off) red[t] += red[t + off];
        __syncthreads();
    }
    if (t == 0) out[0] = red[0] * (1.0f / (float)NROWS);
}

// ---------------- launch (gemm kept 4th for ncu capture) ----------------
extern "C" void kernel_launch(void* const* d_in, const int* in_sizes, int n_in,
                              void* d_out, int out_size) {
    const int*   data  = (const int*)d_in[0];
    const int*   label = (const int*)d_in[1];
    const float* wte   = (const float*)d_in[2];
    const float* wpe   = (const float*)d_in[3];
    const float* W     = (const float*)d_in[4];
    float* out = (float*)d_out;

    cudaFuncSetAttribute(gemm_lse_kernel, cudaFuncAttributeMaxDynamicSharedMemorySize, SMEM_BYTES);

    prep_x_kernel<<<(NROWS * (NEMBD / 4)) / 256, 256>>>(data, wte, wpe);
    conv_w_kernel<<<(VPAD * (NEMBD / 4)) / 256, 256>>>(W);
    label_logit_kernel<<<NROWS / 8, 256>>>(label);
    gemm_lse_kernel<<<dim3(NSPLIT, NROWS / 128), 256, SMEM_BYTES>>>();
    rownll_kernel<<<NROWS / 256, 256>>>();
    reduce_kernel<<<1, 256>>>(out);
}

// round 13
// speedup vs baseline: 1.2257x; 1.0220x over previous
#include <cuda_runtime.h>
#include <cuda_fp16.h>
#include <cstdint>

#define VOCAB   50257
#define VPAD    50304        /* 393 * 128 */
#define NEMBD   768
#define NROWS   8192
#define SEQLEN  1024
#define NSPLIT  10
#define NCHUNK  12           /* 768 / 64 */

#define STAGE_BYTES 24576    /* A chunk 8KB + B chunk 16KB */
#define SMEM_BYTES  (3 * STAGE_BYTES)   /* 73728 -> 3 CTAs/SM */

// ---------------- device scratch ----------------
__device__ __align__(256) __half g_X[(size_t)NROWS * NEMBD];   // fp16(gelu(wte+wpe))
__device__ __align__(256) __half g_W[(size_t)VPAD * NEMBD];    // fp16(W), zero-padded
__device__ float g_pmax[NSPLIT][2][NROWS];
__device__ float g_psum[NSPLIT][2][NROWS];
__device__ float g_ll[NROWS];
__device__ float g_row[NROWS];

// ---------------- helpers ----------------
__device__ __forceinline__ uint32_t smem_u32(const void* p) {
    uint32_t a;
    asm("{ .reg .u64 t; cvta.to.shared.u64 t, %1; cvt.u32.u64 %0, t; }" : "=r"(a) : "l"(p));
    return a;
}
__device__ __forceinline__ void cp_async16(uint32_t dst, const void* src) {
    asm volatile("cp.async.cg.shared.global [%0], [%1], 16;" :: "r"(dst), "l"(src));
}
__device__ __forceinline__ void cp_commit() {
    asm volatile("cp.async.commit_group;" ::: "memory");
}
template <int N>
__device__ __forceinline__ void cp_wait() {
    asm volatile("cp.async.wait_group %0;" :: "n"(N) : "memory");
}
__device__ __forceinline__ void ldsm_x4(uint32_t (&r)[4], uint32_t addr) {
    asm volatile("ldmatrix.sync.aligned.m8n8.x4.shared.b16 {%0,%1,%2,%3}, [%4];"
                 : "=r"(r[0]), "=r"(r[1]), "=r"(r[2]), "=r"(r[3]) : "r"(addr));
}
// fp16 in, fp16 accumulate; D/C are 2x f16x2 regs
__device__ __forceinline__ void mma16816_f16(uint32_t* c, const uint32_t* a, const uint32_t* b) {
    asm volatile(
        "mma.sync.aligned.m16n8k16.row.col.f16.f16.f16.f16 "
        "{%0,%1}, {%2,%3,%4,%5}, {%6,%7}, {%0,%1};"
        : "+r"(c[0]), "+r"(c[1])
        : "r"(a[0]), "r"(a[1]), "r"(a[2]), "r"(a[3]), "r"(b[0]), "r"(b[1]));
}
__device__ __forceinline__ uint32_t swz(uint32_t bo) { return bo ^ ((bo >> 3) & 0x70u); }

// ---------------- kernel: x = fp16(gelu(wte[tok] + wpe[pos])) ----------------
__global__ void prep_x_kernel(const int* __restrict__ data, const float* __restrict__ wte,
                              const float* __restrict__ wpe) {
    int idx = blockIdx.x * blockDim.x + threadIdx.x;
    if (idx >= NROWS * (NEMBD / 4)) return;
    int row = idx / (NEMBD / 4);
    int c4  = idx % (NEMBD / 4);
    int tok = data[row];
    int pos = row & (SEQLEN - 1);
    float4 a = *reinterpret_cast<const float4*>(wte + (size_t)tok * NEMBD + c4 * 4);
    float4 p = *reinterpret_cast<const float4*>(wpe + (size_t)pos * NEMBD + c4 * 4);
    const float K0 = 0.7978845608028654f, K1 = 0.044715f;
    float v[4] = {a.x + p.x, a.y + p.y, a.z + p.z, a.w + p.w};
    float g[4];
#pragma unroll
    for (int i = 0; i < 4; i++) {
        float x = v[i];
        g[i] = 0.5f * x * (1.0f + tanhf(K0 * (x + K1 * x * x * x)));
    }
    __half2* dst = reinterpret_cast<__half2*>(&g_X[(size_t)row * NEMBD + c4 * 4]);
    dst[0] = __floats2half2_rn(g[0], g[1]);
    dst[1] = __floats2half2_rn(g[2], g[3]);
}

// ---------------- kernel: W fp32 -> fp16 (zero-padded rows) ----------------
__global__ void conv_w_kernel(const float* __restrict__ W) {
    int idx = blockIdx.x * blockDim.x + threadIdx.x;
    if (idx >= VPAD * (NEMBD / 4)) return;
    int v  = idx / (NEMBD / 4);
    int c4 = idx % (NEMBD / 4);
    __half2 r0, r1;
    if (v < VOCAB) {
        float4 w = *reinterpret_cast<const float4*>(W + (size_t)v * NEMBD + c4 * 4);
        r0 = __floats2half2_rn(w.x, w.y);
        r1 = __floats2half2_rn(w.z, w.w);
    } else {
        r0 = __floats2half2_rn(0.f, 0.f);
        r1 = r0;
    }
    __half2* dst = reinterpret_cast<__half2*>(&g_W[(size_t)v * NEMBD + c4 * 4]);
    dst[0] = r0;
    dst[1] = r1;
}

// ---------------- kernel: label logits from the SAME fp16 operands ----------------
__global__ void label_logit_kernel(const int* __restrict__ label) {
    int wid = threadIdx.x >> 5, lid = threadIdx.x & 31;
    int row = blockIdx.x * 8 + wid;
    int lab = label[row];
    const __half2* xr = reinterpret_cast<const __half2*>(&g_X[(size_t)row * NEMBD]);
    const __half2* wr = reinterpret_cast<const __half2*>(&g_W[(size_t)lab * NEMBD]);
    float acc = 0.f;
#pragma unroll
    for (int it = 0; it < 12; it++) {
        __half2 x2 = xr[it * 32 + lid];
        __half2 w2 = wr[it * 32 + lid];
        acc += __low2float(x2) * __low2float(w2) + __high2float(x2) * __high2float(w2);
    }
#pragma unroll
    for (int o = 16; o; o >>= 1) acc += __shfl_xor_sync(0xFFFFFFFFu, acc, o);
    if (lid == 0) g_ll[row] = acc;
}

// ---------------- fused GEMM (fp16 mma, fp16 accum) + online logsumexp ----------------
// 128 threads = 4 warps (2M x 2N); warp tile 32x64; CTA tile 64x128.
// A and B streamed via a 3-stage cp.async pipeline (stage = A 8KB + B 16KB = 24KB),
// smem 72KB -> THREE independent CTAs per SM (3 barrier domains, 3 warps/SMSP).
__global__ void __launch_bounds__(128, 3)
gemm_lse_kernel() {
    extern __shared__ char smem[];
    const uint32_t smem_base = smem_u32(smem);
    const int tid  = threadIdx.x;
    const int lane = tid & 31;
    const int wid  = tid >> 5;
    const int wm   = wid >> 1;          // 0..1
    const int wn   = wid & 1;           // 0..1
    const int s    = blockIdx.x;
    const int m0   = blockIdx.y * 64;

    const int rb  = tid >> 3;           // 0..15
    const int seg = tid & 7;            // 0..7
    // A: 64 rows -> 4 lines/thread; B: 128 rows -> 8 lines/thread
    uint32_t cpoA[4], cpoB[8];
#pragma unroll
    for (int j = 0; j < 4; j++)
        cpoA[j] = swz((uint32_t)(rb + 16 * j) * 128u + (uint32_t)seg * 16u);
#pragma unroll
    for (int j = 0; j < 8; j++)
        cpoB[j] = swz((uint32_t)(rb + 16 * j) * 128u + (uint32_t)seg * 16u);

    // vocab tile range: 393 = 3*40 + 7*39
    const int t0   = s * 39 + (s < 3 ? s : 3);
    const int tcnt = 39 + (s < 3 ? 1 : 0);
    const int NC   = tcnt * NCHUNK;

    // A source rows fixed for this CTA
    const __half* aX = &g_X[(size_t)(m0 + rb) * NEMBD + seg * 8];

    // ---- prologue: stages 0 (chunk 0) and 1 (chunk 1), one group each ----
#pragma unroll
    for (int pre = 0; pre < 2; pre++) {
        uint32_t sa = smem_base + pre * STAGE_BYTES;
        uint32_t sb = sa + 8192;
        const __half* srcA = aX + pre * 64;
        const __half* srcB = &g_W[(size_t)(t0 * 128 + rb) * NEMBD + pre * 64 + seg * 8];
#pragma unroll
        for (int j = 0; j < 4; j++)
            cp_async16(sa + cpoA[j], srcA + (size_t)(16 * j) * NEMBD);
#pragma unroll
        for (int j = 0; j < 8; j++)
            cp_async16(sb + cpoB[j], srcB + (size_t)(16 * j) * NEMBD);
        cp_commit();
    }

    // ---- ldmatrix lane constants ----
    const int quad = lane >> 3;
    const int lrow = lane & 7;
    const int a_row = wm * 32 + (quad & 1) * 8 + lrow;
    const int a_c8  = (quad >> 1);
    const int b_row = wn * 64 + (quad >> 1) * 8 + lrow;
    const int b_c8  = (quad & 1);

    float m_run[4], s_run[4];
#pragma unroll
    for (int i = 0; i < 4; i++) { m_run[i] = -3.0e38f; s_run[i] = 0.0f; }

    uint32_t c[2][8][2];
#pragma unroll
    for (int mi = 0; mi < 2; mi++)
#pragma unroll
        for (int nj = 0; nj < 8; nj++) { c[mi][nj][0] = 0u; c[mi][nj][1] = 0u; }

    int v0 = t0 * 128;    // current tile vocab base
    int kk = 0;           // chunk within tile
    int vp = t0 * 128;    // prefetch tile vocab base (chunk g+2)
    int kp = 2;           // prefetch chunk-in-tile
    int st  = 0;          // compute stage
    int pst = 2;          // prefetch stage

#pragma unroll 1
    for (int g = 0; g < NC; g++) {
        cp_wait<1>();
        __syncthreads();

        const uint32_t Ab = smem_base + st * STAGE_BYTES;
        const uint32_t Bb = Ab + 8192;

        // ks = 0 LDSMs first (start loads), then prefetch, then MMAs
        uint32_t a0[2][4], b0[4][4];
#pragma unroll
        for (int mi = 0; mi < 2; mi++) {
            uint32_t bo = (uint32_t)(a_row + mi * 16) * 128u + (uint32_t)(a_c8 * 8) * 2u;
            ldsm_x4(a0[mi], Ab + swz(bo));
        }
#pragma unroll
        for (int p = 0; p < 4; p++) {
            uint32_t bo = (uint32_t)(b_row + p * 16) * 128u + (uint32_t)(b_c8 * 8) * 2u;
            ldsm_x4(b0[p], Bb + swz(bo));
        }

        // prefetch chunk g+2 into stage pst (read last at g-1; safe under the barrier)
        if (g + 2 < NC) {
            uint32_t sa = smem_base + pst * STAGE_BYTES;
            uint32_t sb = sa + 8192;
            const __half* srcA = aX + kp * 64;
            const __half* srcB = &g_W[(size_t)(vp + rb) * NEMBD + kp * 64 + seg * 8];
#pragma unroll
            for (int j = 0; j < 4; j++)
                cp_async16(sa + cpoA[j], srcA + (size_t)(16 * j) * NEMBD);
#pragma unroll
            for (int j = 0; j < 8; j++)
                cp_async16(sb + cpoB[j], srcB + (size_t)(16 * j) * NEMBD);
        }
        cp_commit();
        kp++;
        if (kp == NCHUNK) { kp = 0; vp += 128; }
        pst = (pst == 2) ? 0 : pst + 1;

#pragma unroll
        for (int mi = 0; mi < 2; mi++)
#pragma unroll
            for (int p = 0; p < 4; p++) {
                mma16816_f16(c[mi][p * 2 + 0], a0[mi], &b0[p][0]);
                mma16816_f16(c[mi][p * 2 + 1], a0[mi], &b0[p][2]);
            }

#pragma unroll
        for (int ks = 1; ks < 4; ks++) {
            const int kc = ks * 16;
            uint32_t a[2][4], b[4][4];
#pragma unroll
            for (int mi = 0; mi < 2; mi++) {
                uint32_t bo = (uint32_t)(a_row + mi * 16) * 128u
                            + (uint32_t)(kc + a_c8 * 8) * 2u;
                ldsm_x4(a[mi], Ab + swz(bo));
            }
#pragma unroll
            for (int p = 0; p < 4; p++) {
                uint32_t bo = (uint32_t)(b_row + p * 16) * 128u
                            + (uint32_t)(kc + b_c8 * 8) * 2u;
                ldsm_x4(b[p], Bb + swz(bo));
            }
#pragma unroll
            for (int mi = 0; mi < 2; mi++)
#pragma unroll
                for (int p = 0; p < 4; p++) {
                    mma16816_f16(c[mi][p * 2 + 0], a[mi], &b[p][0]);
                    mma16816_f16(c[mi][p * 2 + 1], a[mi], &b[p][2]);
                }
        }

        st = (st == 2) ? 0 : st + 1;

        kk++;
        if (kk == NCHUNK) {
            // ---- tile epilogue (registers only; co-resident CTAs fill the pipe) ----
            kk = 0;
            const bool edge = (v0 + 128 > VOCAB);
            const int colb = v0 + wn * 64 + 2 * (lane & 3);
#pragma unroll
            for (int sl = 0; sl < 4; sl++) {
                const int mi = sl >> 1, h = sl & 1;
                float vv[8][2];
#pragma unroll
                for (int nj = 0; nj < 8; nj++) {
                    float2 f = __half22float2(*reinterpret_cast<__half2*>(&c[mi][nj][h]));
                    vv[nj][0] = f.x; vv[nj][1] = f.y;
                }
                if (edge) {
#pragma unroll
                    for (int nj = 0; nj < 8; nj++)
#pragma unroll
                        for (int e = 0; e < 2; e++)
                            if (colb + nj * 8 + e >= VOCAB) vv[nj][e] = -3.0e38f;
                }
                float tm = -3.0e38f;
#pragma unroll
                for (int nj = 0; nj < 8; nj++) {
                    tm = fmaxf(tm, vv[nj][0]);
                    tm = fmaxf(tm, vv[nj][1]);
                }
                tm = fmaxf(tm, __shfl_xor_sync(0xFFFFFFFFu, tm, 1));
                tm = fmaxf(tm, __shfl_xor_sync(0xFFFFFFFFu, tm, 2));
                float nm = fmaxf(m_run[sl], tm);
                float p = 0.0f;
#pragma unroll
                for (int nj = 0; nj < 8; nj++) {
                    p += __expf(vv[nj][0] - nm);
                    p += __expf(vv[nj][1] - nm);
                }
                p += __shfl_xor_sync(0xFFFFFFFFu, p, 1);
                p += __shfl_xor_sync(0xFFFFFFFFu, p, 2);
                s_run[sl] = s_run[sl] * __expf(m_run[sl] - nm) + p;
                m_run[sl] = nm;
            }
            v0 += 128;
#pragma unroll
            for (int mi = 0; mi < 2; mi++)
#pragma unroll
                for (int nj = 0; nj < 8; nj++) { c[mi][nj][0] = 0u; c[mi][nj][1] = 0u; }
        }
    }

    // ---- store per-row partials keyed by (s, wn) ----
    if ((lane & 3) == 0) {
#pragma unroll
        for (int sl = 0; sl < 4; sl++) {
            const int mi = sl >> 1, h = sl & 1;
            int row = m0 + wm * 32 + mi * 16 + h * 8 + (lane >> 2);
            g_pmax[s][wn][row] = m_run[sl];
            g_psum[s][wn][row] = s_run[sl];
        }
    }
}

// ---------------- kernel: per-row NLL ----------------
__global__ void rownll_kernel() {
    int r = blockIdx.x * 256 + threadIdx.x;
    float m = g_pmax[0][0][r];
#pragma unroll
    for (int s = 0; s < NSPLIT; s++) {
        m = fmaxf(m, g_pmax[s][0][r]);
        m = fmaxf(m, g_pmax[s][1][r]);
    }
    float S = 0.f;
#pragma unroll
    for (int s = 0; s < NSPLIT; s++) {
        S += g_psum[s][0][r] * __expf(g_pmax[s][0][r] - m);
        S += g_psum[s][1][r] * __expf(g_pmax[s][1][r] - m);
    }
    g_row[r] = (m + logf(S)) - g_ll[r];
}

// ---------------- kernel: deterministic mean ----------------
__global__ void reduce_kernel(float* __restrict__ out) {
    __shared__ float red[256];
    int t = threadIdx.x;
    float local = 0.f;
#pragma unroll
    for (int i = 0; i < NROWS / 256; i++) local += g_row[t + i * 256];
    red[t] = local;
    __syncthreads();
    for (int off = 128; off; off >>= 1) {
        if (t < off) red[t] += red[t + off];
        __syncthreads();
    }
    if (t == 0) out[0] = red[0] * (1.0f / (float)NROWS);
}

// ---------------- launch (gemm kept 4th for ncu capture) ----------------
extern "C" void kernel_launch(void* const* d_in, const int* in_sizes, int n_in,
                              void* d_out, int out_size) {
    const int*   data  = (const int*)d_in[0];
    const int*   label = (const int*)d_in[1];
    const float* wte   = (const float*)d_in[2];
    const float* wpe   = (const float*)d_in[3];
    const float* W     = (const float*)d_in[4];
    float* out = (float*)d_out;

    cudaFuncSetAttribute(gemm_lse_kernel, cudaFuncAttributeMaxDynamicSharedMemorySize, SMEM_BYTES);

    prep_x_kernel<<<(NROWS * (NEMBD / 4)) / 256, 256>>>(data, wte, wpe);
    conv_w_kernel<<<(VPAD * (NEMBD / 4)) / 256, 256>>>(W);
    label_logit_kernel<<<NROWS / 8, 256>>>(label);
    gemm_lse_kernel<<<dim3(NSPLIT, NROWS / 64), 128, SMEM_BYTES>>>();
    rownll_kernel<<<NROWS / 256, 256>>>();
    reduce_kernel<<<1, 256>>>(out);
}

// round 14
// speedup vs baseline: 1.3620x; 1.1112x over previous
#include <cuda_runtime.h>
#include <cuda_fp16.h>
#include <cstdint>

#define VOCAB   50257
#define VPAD    50304        /* 393 * 128 */
#define NEMBD   768
#define NROWS   8192
#define SEQLEN  1024
#define NSPLIT  14
#define NCHUNK  12           /* 768 / 64 */

#define STAGE_BYTES 24576    /* A chunk 8KB + B chunk 16KB */
#define SMEM_BYTES  (2 * STAGE_BYTES)   /* 49152 -> 4 CTAs/SM */

// ---------------- device scratch ----------------
__device__ __align__(256) __half g_X[(size_t)NROWS * NEMBD];   // fp16(gelu(wte+wpe))
__device__ __align__(256) __half g_W[(size_t)VPAD * NEMBD];    // fp16(W), zero-padded
__device__ float g_pmax[NSPLIT][2][NROWS];
__device__ float g_psum[NSPLIT][2][NROWS];
__device__ float g_ll[NROWS];
__device__ float g_row[NROWS];

// ---------------- helpers ----------------
__device__ __forceinline__ uint32_t smem_u32(const void* p) {
    uint32_t a;
    asm("{ .reg .u64 t; cvta.to.shared.u64 t, %1; cvt.u32.u64 %0, t; }" : "=r"(a) : "l"(p));
    return a;
}
__device__ __forceinline__ void cp_async16(uint32_t dst, const void* src) {
    asm volatile("cp.async.cg.shared.global [%0], [%1], 16;" :: "r"(dst), "l"(src));
}
__device__ __forceinline__ void cp_commit() {
    asm volatile("cp.async.commit_group;" ::: "memory");
}
template <int N>
__device__ __forceinline__ void cp_wait() {
    asm volatile("cp.async.wait_group %0;" :: "n"(N) : "memory");
}
__device__ __forceinline__ void ldsm_x4(uint32_t (&r)[4], uint32_t addr) {
    asm volatile("ldmatrix.sync.aligned.m8n8.x4.shared.b16 {%0,%1,%2,%3}, [%4];"
                 : "=r"(r[0]), "=r"(r[1]), "=r"(r[2]), "=r"(r[3]) : "r"(addr));
}
// fp16 in, fp16 accumulate; D/C are 2x f16x2 regs
__device__ __forceinline__ void mma16816_f16(uint32_t* c, const uint32_t* a, const uint32_t* b) {
    asm volatile(
        "mma.sync.aligned.m16n8k16.row.col.f16.f16.f16.f16 "
        "{%0,%1}, {%2,%3,%4,%5}, {%6,%7}, {%0,%1};"
        : "+r"(c[0]), "+r"(c[1])
        : "r"(a[0]), "r"(a[1]), "r"(a[2]), "r"(a[3]), "r"(b[0]), "r"(b[1]));
}
__device__ __forceinline__ uint32_t swz(uint32_t bo) { return bo ^ ((bo >> 3) & 0x70u); }

// ---------------- kernel: x = fp16(gelu(wte[tok] + wpe[pos])) ----------------
__global__ void prep_x_kernel(const int* __restrict__ data, const float* __restrict__ wte,
                              const float* __restrict__ wpe) {
    int idx = blockIdx.x * blockDim.x + threadIdx.x;
    if (idx >= NROWS * (NEMBD / 4)) return;
    int row = idx / (NEMBD / 4);
    int c4  = idx % (NEMBD / 4);
    int tok = data[row];
    int pos = row & (SEQLEN - 1);
    float4 a = *reinterpret_cast<const float4*>(wte + (size_t)tok * NEMBD + c4 * 4);
    float4 p = *reinterpret_cast<const float4*>(wpe + (size_t)pos * NEMBD + c4 * 4);
    const float K0 = 0.7978845608028654f, K1 = 0.044715f;
    float v[4] = {a.x + p.x, a.y + p.y, a.z + p.z, a.w + p.w};
    float g[4];
#pragma unroll
    for (int i = 0; i < 4; i++) {
        float x = v[i];
        g[i] = 0.5f * x * (1.0f + tanhf(K0 * (x + K1 * x * x * x)));
    }
    __half2* dst = reinterpret_cast<__half2*>(&g_X[(size_t)row * NEMBD + c4 * 4]);
    dst[0] = __floats2half2_rn(g[0], g[1]);
    dst[1] = __floats2half2_rn(g[2], g[3]);
}

// ---------------- kernel: W fp32 -> fp16 (zero-padded rows) ----------------
__global__ void conv_w_kernel(const float* __restrict__ W) {
    int idx = blockIdx.x * blockDim.x + threadIdx.x;
    if (idx >= VPAD * (NEMBD / 4)) return;
    int v  = idx / (NEMBD / 4);
    int c4 = idx % (NEMBD / 4);
    __half2 r0, r1;
    if (v < VOCAB) {
        float4 w = *reinterpret_cast<const float4*>(W + (size_t)v * NEMBD + c4 * 4);
        r0 = __floats2half2_rn(w.x, w.y);
        r1 = __floats2half2_rn(w.z, w.w);
    } else {
        r0 = __floats2half2_rn(0.f, 0.f);
        r1 = r0;
    }
    __half2* dst = reinterpret_cast<__half2*>(&g_W[(size_t)v * NEMBD + c4 * 4]);
    dst[0] = r0;
    dst[1] = r1;
}

// ---------------- kernel: label logits from the SAME fp16 operands ----------------
__global__ void label_logit_kernel(const int* __restrict__ label) {
    int wid = threadIdx.x >> 5, lid = threadIdx.x & 31;
    int row = blockIdx.x * 8 + wid;
    int lab = label[row];
    const __half2* xr = reinterpret_cast<const __half2*>(&g_X[(size_t)row * NEMBD]);
    const __half2* wr = reinterpret_cast<const __half2*>(&g_W[(size_t)lab * NEMBD]);
    float acc = 0.f;
#pragma unroll
    for (int it = 0; it < 12; it++) {
        __half2 x2 = xr[it * 32 + lid];
        __half2 w2 = wr[it * 32 + lid];
        acc += __low2float(x2) * __low2float(w2) + __high2float(x2) * __high2float(w2);
    }
#pragma unroll
    for (int o = 16; o; o >>= 1) acc += __shfl_xor_sync(0xFFFFFFFFu, acc, o);
    if (lid == 0) g_ll[row] = acc;
}

// ---------------- fused GEMM (fp16 mma, fp16 accum) + online logsumexp ----------------
// 128 threads = 4 warps (2M x 2N); warp tile 32x64; CTA tile 64x128.
// A and B streamed via a 2-stage cp.async pipeline (stage = A 8KB + B 16KB = 24KB),
// smem 48KB -> FOUR independent CTAs per SM (4 barrier domains, 4 warps/SMSP).
// Prefetch: mid-chunk, distance 1 (R6 pattern); residual wait hidden by co-CTAs.
__global__ void __launch_bounds__(128, 4)
gemm_lse_kernel() {
    extern __shared__ char smem[];
    const uint32_t smem_base = smem_u32(smem);
    const int tid  = threadIdx.x;
    const int lane = tid & 31;
    const int wid  = tid >> 5;
    const int wm   = wid >> 1;          // 0..1
    const int wn   = wid & 1;           // 0..1
    const int s    = blockIdx.x;
    const int m0   = blockIdx.y * 64;

    const int rb  = tid >> 3;           // 0..15
    const int seg = tid & 7;            // 0..7
    // A: 64 rows -> 4 lines/thread; B: 128 rows -> 8 lines/thread
    uint32_t cpoA[4], cpoB[8];
#pragma unroll
    for (int j = 0; j < 4; j++)
        cpoA[j] = swz((uint32_t)(rb + 16 * j) * 128u + (uint32_t)seg * 16u);
#pragma unroll
    for (int j = 0; j < 8; j++)
        cpoB[j] = swz((uint32_t)(rb + 16 * j) * 128u + (uint32_t)seg * 16u);

    // vocab tile range: 393 = 1*29 + 13*28
    const int t0   = s * 28 + (s < 1 ? 0 : 1);
    const int tcnt = 28 + (s < 1 ? 1 : 0);
    const int NC   = tcnt * NCHUNK;

    // A source rows fixed for this CTA
    const __half* aX = &g_X[(size_t)(m0 + rb) * NEMBD + seg * 8];

    // ---- prologue: chunk 0 into stage 0 ----
    {
        uint32_t sa = smem_base;
        uint32_t sb = sa + 8192;
        const __half* srcB = &g_W[(size_t)(t0 * 128 + rb) * NEMBD + seg * 8];
#pragma unroll
        for (int j = 0; j < 4; j++)
            cp_async16(sa + cpoA[j], aX + (size_t)(16 * j) * NEMBD);
#pragma unroll
        for (int j = 0; j < 8; j++)
            cp_async16(sb + cpoB[j], srcB + (size_t)(16 * j) * NEMBD);
        cp_commit();
    }

    // ---- ldmatrix lane constants ----
    const int quad = lane >> 3;
    const int lrow = lane & 7;
    const int a_row = wm * 32 + (quad & 1) * 8 + lrow;
    const int a_c8  = (quad >> 1);
    const int b_row = wn * 64 + (quad >> 1) * 8 + lrow;
    const int b_c8  = (quad & 1);

    float m_run[4], s_run[4];
#pragma unroll
    for (int i = 0; i < 4; i++) { m_run[i] = -3.0e38f; s_run[i] = 0.0f; }

    uint32_t c[2][8][2];
#pragma unroll
    for (int mi = 0; mi < 2; mi++)
#pragma unroll
        for (int nj = 0; nj < 8; nj++) { c[mi][nj][0] = 0u; c[mi][nj][1] = 0u; }

    int v0 = t0 * 128;    // current tile vocab base
    int kk = 0;           // chunk within tile
    int vp = t0 * 128;    // prefetch tile vocab base (chunk g+1)
    int kp = 1;           // prefetch chunk-in-tile

#pragma unroll 1
    for (int g = 0; g < NC; g++) {
        cp_wait<0>();
        __syncthreads();

        const uint32_t Ab = smem_base + (g & 1) * STAGE_BYTES;
        const uint32_t Bb = Ab + 8192;

        // ks = 0 LDSMs first (start loads), then prefetch, then MMAs
        uint32_t a0[2][4], b0[4][4];
#pragma unroll
        for (int mi = 0; mi < 2; mi++) {
            uint32_t bo = (uint32_t)(a_row + mi * 16) * 128u + (uint32_t)(a_c8 * 8) * 2u;
            ldsm_x4(a0[mi], Ab + swz(bo));
        }
#pragma unroll
        for (int p = 0; p < 4; p++) {
            uint32_t bo = (uint32_t)(b_row + p * 16) * 128u + (uint32_t)(b_c8 * 8) * 2u;
            ldsm_x4(b0[p], Bb + swz(bo));
        }

        // prefetch chunk g+1 into the other stage (read last at g-1; barrier-safe)
        if (g + 1 < NC) {
            uint32_t sa = smem_base + ((g + 1) & 1) * STAGE_BYTES;
            uint32_t sb = sa + 8192;
            const __half* srcA = aX + kp * 64;
            const __half* srcB = &g_W[(size_t)(vp + rb) * NEMBD + kp * 64 + seg * 8];
#pragma unroll
            for (int j = 0; j < 4; j++)
                cp_async16(sa + cpoA[j], srcA + (size_t)(16 * j) * NEMBD);
#pragma unroll
            for (int j = 0; j < 8; j++)
                cp_async16(sb + cpoB[j], srcB + (size_t)(16 * j) * NEMBD);
        }
        cp_commit();
        kp++;
        if (kp == NCHUNK) { kp = 0; vp += 128; }

#pragma unroll
        for (int mi = 0; mi < 2; mi++)
#pragma unroll
            for (int p = 0; p < 4; p++) {
                mma16816_f16(c[mi][p * 2 + 0], a0[mi], &b0[p][0]);
                mma16816_f16(c[mi][p * 2 + 1], a0[mi], &b0[p][2]);
            }

#pragma unroll
        for (int ks = 1; ks < 4; ks++) {
            const int kc = ks * 16;
            uint32_t a[2][4], b[4][4];
#pragma unroll
            for (int mi = 0; mi < 2; mi++) {
                uint32_t bo = (uint32_t)(a_row + mi * 16) * 128u
                            + (uint32_t)(kc + a_c8 * 8) * 2u;
                ldsm_x4(a[mi], Ab + swz(bo));
            }
#pragma unroll
            for (int p = 0; p < 4; p++) {
                uint32_t bo = (uint32_t)(b_row + p * 16) * 128u
                            + (uint32_t)(kc + b_c8 * 8) * 2u;
                ldsm_x4(b[p], Bb + swz(bo));
            }
#pragma unroll
            for (int mi = 0; mi < 2; mi++)
#pragma unroll
                for (int p = 0; p < 4; p++) {
                    mma16816_f16(c[mi][p * 2 + 0], a[mi], &b[p][0]);
                    mma16816_f16(c[mi][p * 2 + 1], a[mi], &b[p][2]);
                }
        }

        kk++;
        if (kk == NCHUNK) {
            // ---- tile epilogue (registers only; co-resident CTAs fill the pipe) ----
            kk = 0;
            const bool edge = (v0 + 128 > VOCAB);
            const int colb = v0 + wn * 64 + 2 * (lane & 3);
#pragma unroll
            for (int sl = 0; sl < 4; sl++) {
                const int mi = sl >> 1, h = sl & 1;
                float vv[8][2];
#pragma unroll
                for (int nj = 0; nj < 8; nj++) {
                    float2 f = __half22float2(*reinterpret_cast<__half2*>(&c[mi][nj][h]));
                    vv[nj][0] = f.x; vv[nj][1] = f.y;
                }
                if (edge) {
#pragma unroll
                    for (int nj = 0; nj < 8; nj++)
#pragma unroll
                        for (int e = 0; e < 2; e++)
                            if (colb + nj * 8 + e >= VOCAB) vv[nj][e] = -3.0e38f;
                }
                float tm = -3.0e38f;
#pragma unroll
                for (int nj = 0; nj < 8; nj++) {
                    tm = fmaxf(tm, vv[nj][0]);
                    tm = fmaxf(tm, vv[nj][1]);
                }
                tm = fmaxf(tm, __shfl_xor_sync(0xFFFFFFFFu, tm, 1));
                tm = fmaxf(tm, __shfl_xor_sync(0xFFFFFFFFu, tm, 2));
                float nm = fmaxf(m_run[sl], tm);
                float p = 0.0f;
#pragma unroll
                for (int nj = 0; nj < 8; nj++) {
                    p += __expf(vv[nj][0] - nm);
                    p += __expf(vv[nj][1] - nm);
                }
                p += __shfl_xor_sync(0xFFFFFFFFu, p, 1);
                p += __shfl_xor_sync(0xFFFFFFFFu, p, 2);
                s_run[sl] = s_run[sl] * __expf(m_run[sl] - nm) + p;
                m_run[sl] = nm;
            }
            v0 += 128;
#pragma unroll
            for (int mi = 0; mi < 2; mi++)
#pragma unroll
                for (int nj = 0; nj < 8; nj++) { c[mi][nj][0] = 0u; c[mi][nj][1] = 0u; }
        }
    }

    // ---- store per-row partials keyed by (s, wn) ----
    if ((lane & 3) == 0) {
#pragma unroll
        for (int sl = 0; sl < 4; sl++) {
            const int mi = sl >> 1, h = sl & 1;
            int row = m0 + wm * 32 + mi * 16 + h * 8 + (lane >> 2);
            g_pmax[s][wn][row] = m_run[sl];
            g_psum[s][wn][row] = s_run[sl];
        }
    }
}

// ---------------- kernel: per-row NLL ----------------
__global__ void rownll_kernel() {
    int r = blockIdx.x * 256 + threadIdx.x;
    float m = g_pmax[0][0][r];
#pragma unroll
    for (int s = 0; s < NSPLIT; s++) {
        m = fmaxf(m, g_pmax[s][0][r]);
        m = fmaxf(m, g_pmax[s][1][r]);
    }
    float S = 0.f;
#pragma unroll
    for (int s = 0; s < NSPLIT; s++) {
        S += g_psum[s][0][r] * __expf(g_pmax[s][0][r] - m);
        S += g_psum[s][1][r] * __expf(g_pmax[s][1][r] - m);
    }
    g_row[r] = (m + logf(S)) - g_ll[r];
}

// ---------------- kernel: deterministic mean ----------------
__global__ void reduce_kernel(float* __restrict__ out) {
    __shared__ float red[256];
    int t = threadIdx.x;
    float local = 0.f;
#pragma unroll
    for (int i = 0; i < NROWS / 256; i++) local += g_row[t + i * 256];
    red[t] = local;
    __syncthreads();
    for (int off = 128; off; off >>= 1) {
        if (t < off) red[t] += red[t + off];
        __syncthreads();
    }
    if (t == 0) out[0] = red[0] * (1.0f / (float)NROWS);
}

// ---------------- launch (gemm kept 4th for ncu capture) ----------------
extern "C" void kernel_launch(void* const* d_in, const int* in_sizes, int n_in,
                              void* d_out, int out_size) {
    const int*   data  = (const int*)d_in[0];
    const int*   label = (const int*)d_in[1];
    const float* wte   = (const float*)d_in[2];
    const float* wpe   = (const float*)d_in[3];
    const float* W     = (const float*)d_in[4];
    float* out = (float*)d_out;

    cudaFuncSetAttribute(gemm_lse_kernel, cudaFuncAttributeMaxDynamicSharedMemorySize, SMEM_BYTES);

    prep_x_kernel<<<(NROWS * (NEMBD / 4)) / 256, 256>>>(data, wte, wpe);
    conv_w_kernel<<<(VPAD * (NEMBD / 4)) / 256, 256>>>(W);
    label_logit_kernel<<<NROWS / 8, 256>>>(label);
    gemm_lse_kernel<<<dim3(NSPLIT, NROWS / 64), 128, SMEM_BYTES>>>();
    rownll_kernel<<<NROWS / 256, 256>>>();
    reduce_kernel<<<1, 256>>>(out);
}

// round 15
// speedup vs baseline: 1.3792x; 1.0126x over previous
#include <cuda_runtime.h>
#include <cuda_fp16.h>
#include <cstdint>

#define VOCAB   50257
#define VPAD    50304        /* 393 * 128 */
#define NEMBD   768
#define NROWS   8192
#define SEQLEN  1024
#define NSPLIT  14
#define NCHUNK  12           /* 768 / 64 */

#define STAGE_BYTES 24576    /* A chunk 8KB + B chunk 16KB */
#define SMEM_BYTES  (2 * STAGE_BYTES)   /* 49152 -> 4 CTAs/SM */

// ---------------- device scratch ----------------
__device__ __align__(256) __half g_X[(size_t)NROWS * NEMBD];   // fp16(gelu(wte+wpe))
__device__ __align__(256) __half g_W[(size_t)VPAD * NEMBD];    // fp16(W), zero-padded
__device__ float g_pmax[NSPLIT][2][NROWS];
__device__ float g_psum[NSPLIT][2][NROWS];
__device__ float g_ll[NROWS];
__device__ float g_row[NROWS];

// ---------------- helpers ----------------
__device__ __forceinline__ uint32_t smem_u32(const void* p) {
    uint32_t a;
    asm("{ .reg .u64 t; cvta.to.shared.u64 t, %1; cvt.u32.u64 %0, t; }" : "=r"(a) : "l"(p));
    return a;
}
__device__ __forceinline__ void cp_async16(uint32_t dst, const void* src) {
    asm volatile("cp.async.cg.shared.global [%0], [%1], 16;" :: "r"(dst), "l"(src));
}
__device__ __forceinline__ void cp_commit() {
    asm volatile("cp.async.commit_group;" ::: "memory");
}
template <int N>
__device__ __forceinline__ void cp_wait() {
    asm volatile("cp.async.wait_group %0;" :: "n"(N) : "memory");
}
__device__ __forceinline__ void ldsm_x4(uint32_t (&r)[4], uint32_t addr) {
    asm volatile("ldmatrix.sync.aligned.m8n8.x4.shared.b16 {%0,%1,%2,%3}, [%4];"
                 : "=r"(r[0]), "=r"(r[1]), "=r"(r[2]), "=r"(r[3]) : "r"(addr));
}
// fp16 in, fp16 accumulate; D/C are 2x f16x2 regs
__device__ __forceinline__ void mma16816_f16(uint32_t* c, const uint32_t* a, const uint32_t* b) {
    asm volatile(
        "mma.sync.aligned.m16n8k16.row.col.f16.f16.f16.f16 "
        "{%0,%1}, {%2,%3,%4,%5}, {%6,%7}, {%0,%1};"
        : "+r"(c[0]), "+r"(c[1])
        : "r"(a[0]), "r"(a[1]), "r"(a[2]), "r"(a[3]), "r"(b[0]), "r"(b[1]));
}
__device__ __forceinline__ uint32_t swz(uint32_t bo) { return bo ^ ((bo >> 3) & 0x70u); }

// ---------------- kernel: x = fp16(gelu(wte[tok] + wpe[pos])) ----------------
__global__ void prep_x_kernel(const int* __restrict__ data, const float* __restrict__ wte,
                              const float* __restrict__ wpe) {
    int idx = blockIdx.x * blockDim.x + threadIdx.x;
    if (idx >= NROWS * (NEMBD / 4)) return;
    int row = idx / (NEMBD / 4);
    int c4  = idx % (NEMBD / 4);
    int tok = data[row];
    int pos = row & (SEQLEN - 1);
    float4 a = *reinterpret_cast<const float4*>(wte + (size_t)tok * NEMBD + c4 * 4);
    float4 p = *reinterpret_cast<const float4*>(wpe + (size_t)pos * NEMBD + c4 * 4);
    const float K0 = 0.7978845608028654f, K1 = 0.044715f;
    float v[4] = {a.x + p.x, a.y + p.y, a.z + p.z, a.w + p.w};
    float g[4];
#pragma unroll
    for (int i = 0; i < 4; i++) {
        float x = v[i];
        g[i] = 0.5f * x * (1.0f + tanhf(K0 * (x + K1 * x * x * x)));
    }
    __half2* dst = reinterpret_cast<__half2*>(&g_X[(size_t)row * NEMBD + c4 * 4]);
    dst[0] = __floats2half2_rn(g[0], g[1]);
    dst[1] = __floats2half2_rn(g[2], g[3]);
}

// ---------------- kernel: W fp32 -> fp16 (zero-padded rows) ----------------
__global__ void conv_w_kernel(const float* __restrict__ W) {
    int idx = blockIdx.x * blockDim.x + threadIdx.x;
    if (idx >= VPAD * (NEMBD / 4)) return;
    int v  = idx / (NEMBD / 4);
    int c4 = idx % (NEMBD / 4);
    __half2 r0, r1;
    if (v < VOCAB) {
        float4 w = *reinterpret_cast<const float4*>(W + (size_t)v * NEMBD + c4 * 4);
        r0 = __floats2half2_rn(w.x, w.y);
        r1 = __floats2half2_rn(w.z, w.w);
    } else {
        r0 = __floats2half2_rn(0.f, 0.f);
        r1 = r0;
    }
    __half2* dst = reinterpret_cast<__half2*>(&g_W[(size_t)v * NEMBD + c4 * 4]);
    dst[0] = r0;
    dst[1] = r1;
}

// ---------------- kernel: label logits from the SAME fp16 operands ----------------
__global__ void label_logit_kernel(const int* __restrict__ label) {
    int wid = threadIdx.x >> 5, lid = threadIdx.x & 31;
    int row = blockIdx.x * 8 + wid;
    int lab = label[row];
    const __half2* xr = reinterpret_cast<const __half2*>(&g_X[(size_t)row * NEMBD]);
    const __half2* wr = reinterpret_cast<const __half2*>(&g_W[(size_t)lab * NEMBD]);
    float acc = 0.f;
#pragma unroll
    for (int it = 0; it < 12; it++) {
        __half2 x2 = xr[it * 32 + lid];
        __half2 w2 = wr[it * 32 + lid];
        acc += __low2float(x2) * __low2float(w2) + __high2float(x2) * __high2float(w2);
    }
#pragma unroll
    for (int o = 16; o; o >>= 1) acc += __shfl_xor_sync(0xFFFFFFFFu, acc, o);
    if (lid == 0) g_ll[row] = acc;
}

// ---------------- fused GEMM (fp16 mma, fp16 accum) + online logsumexp ----------------
// 128 threads = 4 warps (2M x 2N); warp tile 32x64; CTA tile 64x128.
// 2-stage cp.async pipeline (stage = A 8KB + B 16KB), 4 CTAs/SM (4 barrier domains).
// R15: LDSM addresses algebraically hoisted — swz(row*128+col) = row*128 + (col^((row&7)<<4)),
// and row+16k preserves row&7 -> per-ldsm address = stage_base + const. B gmem source kept
// as a per-tile base pointer (64-bit mul only at tile wrap).
__global__ void __launch_bounds__(128, 4)
gemm_lse_kernel() {
    extern __shared__ char smem[];
    const uint32_t smem_base = smem_u32(smem);
    const int tid  = threadIdx.x;
    const int lane = tid & 31;
    const int wid  = tid >> 5;
    const int wm   = wid >> 1;          // 0..1
    const int wn   = wid & 1;           // 0..1
    const int s    = blockIdx.x;
    const int m0   = blockIdx.y * 64;

    const int rb  = tid >> 3;           // 0..15
    const int seg = tid & 7;            // 0..7
    uint32_t cpoA[4], cpoB[8];
#pragma unroll
    for (int j = 0; j < 4; j++)
        cpoA[j] = swz((uint32_t)(rb + 16 * j) * 128u + (uint32_t)seg * 16u);
#pragma unroll
    for (int j = 0; j < 8; j++)
        cpoB[j] = swz((uint32_t)(rb + 16 * j) * 128u + (uint32_t)seg * 16u);

    // vocab tile range: 393 = 1*29 + 13*28
    const int t0   = s * 28 + (s < 1 ? 0 : 1);
    const int tcnt = 28 + (s < 1 ? 1 : 0);
    const int NC   = tcnt * NCHUNK;

    // gmem source base pointers (A fixed; B advanced once per tile)
    const __half* aX = &g_X[(size_t)(m0 + rb) * NEMBD + seg * 8];
    const __half* bW = &g_W[(size_t)(t0 * 128 + rb) * NEMBD + seg * 8];

    // ---- prologue: chunk 0 into stage 0 ----
    {
        uint32_t sa = smem_base;
        uint32_t sb = sa + 8192;
#pragma unroll
        for (int j = 0; j < 4; j++)
            cp_async16(sa + cpoA[j], aX + (size_t)(16 * j) * NEMBD);
#pragma unroll
        for (int j = 0; j < 8; j++)
            cp_async16(sb + cpoB[j], bW + (size_t)(16 * j) * NEMBD);
        cp_commit();
    }

    // ---- ldmatrix lane constants (hoisted swizzle algebra) ----
    const int quad = lane >> 3;
    const int lrow = lane & 7;
    const int a_row = wm * 32 + (quad & 1) * 8 + lrow;     // + mi*16 (row&7 invariant)
    const int b_row = wn * 64 + (quad >> 1) * 8 + lrow;    // + p*16  (row&7 invariant)
    const uint32_t a_rowoff = (uint32_t)a_row * 128u;
    const uint32_t b_rowoff = (uint32_t)b_row * 128u;
    const uint32_t xorA = ((uint32_t)a_row & 7u) << 4;
    const uint32_t xorB = ((uint32_t)b_row & 7u) << 4;
    uint32_t acol[4], bcol[4];
#pragma unroll
    for (int ks = 0; ks < 4; ks++) {
        acol[ks] = ((uint32_t)(ks * 16 + (quad >> 1) * 8) * 2u) ^ xorA;
        bcol[ks] = ((uint32_t)(ks * 16 + (quad & 1) * 8) * 2u) ^ xorB;
    }

    float m_run[4], s_run[4];
#pragma unroll
    for (int i = 0; i < 4; i++) { m_run[i] = -3.0e38f; s_run[i] = 0.0f; }

    uint32_t c[2][8][2];
#pragma unroll
    for (int mi = 0; mi < 2; mi++)
#pragma unroll
        for (int nj = 0; nj < 8; nj++) { c[mi][nj][0] = 0u; c[mi][nj][1] = 0u; }

    int v0 = t0 * 128;    // current tile vocab base
    int kk = 0;           // chunk within tile
    int kp = 1;           // prefetch chunk-in-tile

#pragma unroll 1
    for (int g = 0; g < NC; g++) {
        cp_wait<0>();
        __syncthreads();

        const uint32_t Ab = smem_base + (g & 1) * STAGE_BYTES;
        const uint32_t Bb = Ab + 8192;
        const uint32_t aBase = Ab + a_rowoff;          // + mi*2048 + acol[ks]
        const uint32_t bBase = Bb + 8192u - 8192u + b_rowoff;  // (Bb + b_rowoff)

        // ks = 0 LDSMs first (start loads), then prefetch, then MMAs
        uint32_t a0[2][4], b0[4][4];
#pragma unroll
        for (int mi = 0; mi < 2; mi++)
            ldsm_x4(a0[mi], aBase + mi * 2048u + acol[0]);
#pragma unroll
        for (int p = 0; p < 4; p++)
            ldsm_x4(b0[p], bBase + p * 2048u + bcol[0]);

        // prefetch chunk g+1 into the other stage (read last at g-1; barrier-safe)
        if (g + 1 < NC) {
            uint32_t sa = smem_base + ((g + 1) & 1) * STAGE_BYTES;
            uint32_t sb = sa + 8192;
            const __half* srcA = aX + kp * 64;
            const __half* srcB = bW + kp * 64;
#pragma unroll
            for (int j = 0; j < 4; j++)
                cp_async16(sa + cpoA[j], srcA + (size_t)(16 * j) * NEMBD);
#pragma unroll
            for (int j = 0; j < 8; j++)
                cp_async16(sb + cpoB[j], srcB + (size_t)(16 * j) * NEMBD);
        }
        cp_commit();
        kp++;
        if (kp == NCHUNK) { kp = 0; bW += (size_t)128 * NEMBD; }

#pragma unroll
        for (int mi = 0; mi < 2; mi++)
#pragma unroll
            for (int p = 0; p < 4; p++) {
                mma16816_f16(c[mi][p * 2 + 0], a0[mi], &b0[p][0]);
                mma16816_f16(c[mi][p * 2 + 1], a0[mi], &b0[p][2]);
            }

#pragma unroll
        for (int ks = 1; ks < 4; ks++) {
            uint32_t a[2][4], b[4][4];
#pragma unroll
            for (int mi = 0; mi < 2; mi++)
                ldsm_x4(a[mi], aBase + mi * 2048u + acol[ks]);
#pragma unroll
            for (int p = 0; p < 4; p++)
                ldsm_x4(b[p], bBase + p * 2048u + bcol[ks]);
#pragma unroll
            for (int mi = 0; mi < 2; mi++)
#pragma unroll
                for (int p = 0; p < 4; p++) {
                    mma16816_f16(c[mi][p * 2 + 0], a[mi], &b[p][0]);
                    mma16816_f16(c[mi][p * 2 + 1], a[mi], &b[p][2]);
                }
        }

        kk++;
        if (kk == NCHUNK) {
            // ---- tile epilogue (registers only; co-resident CTAs fill the pipe) ----
            kk = 0;
            const bool edge = (v0 + 128 > VOCAB);
            const int colb = v0 + wn * 64 + 2 * (lane & 3);
#pragma unroll
            for (int sl = 0; sl < 4; sl++) {
                const int mi = sl >> 1, h = sl & 1;
                float vv[8][2];
#pragma unroll
                for (int nj = 0; nj < 8; nj++) {
                    float2 f = __half22float2(*reinterpret_cast<__half2*>(&c[mi][nj][h]));
                    vv[nj][0] = f.x; vv[nj][1] = f.y;
                }
                if (edge) {
#pragma unroll
                    for (int nj = 0; nj < 8; nj++)
#pragma unroll
                        for (int e = 0; e < 2; e++)
                            if (colb + nj * 8 + e >= VOCAB) vv[nj][e] = -3.0e38f;
                }
                float tm = -3.0e38f;
#pragma unroll
                for (int nj = 0; nj < 8; nj++) {
                    tm = fmaxf(tm, vv[nj][0]);
                    tm = fmaxf(tm, vv[nj][1]);
                }
                tm = fmaxf(tm, __shfl_xor_sync(0xFFFFFFFFu, tm, 1));
                tm = fmaxf(tm, __shfl_xor_sync(0xFFFFFFFFu, tm, 2));
                float nm = fmaxf(m_run[sl], tm);
                float p = 0.0f;
#pragma unroll
                for (int nj = 0; nj < 8; nj++) {
                    p += __expf(vv[nj][0] - nm);
                    p += __expf(vv[nj][1] - nm);
                }
                p += __shfl_xor_sync(0xFFFFFFFFu, p, 1);
                p += __shfl_xor_sync(0xFFFFFFFFu, p, 2);
                s_run[sl] = s_run[sl] * __expf(m_run[sl] - nm) + p;
                m_run[sl] = nm;
            }
            v0 += 128;
#pragma unroll
            for (int mi = 0; mi < 2; mi++)
#pragma unroll
                for (int nj = 0; nj < 8; nj++) { c[mi][nj][0] = 0u; c[mi][nj][1] = 0u; }
        }
    }

    // ---- store per-row partials keyed by (s, wn) ----
    if ((lane & 3) == 0) {
#pragma unroll
        for (int sl = 0; sl < 4; sl++) {
            const int mi = sl >> 1, h = sl & 1;
            int row = m0 + wm * 32 + mi * 16 + h * 8 + (lane >> 2);
            g_pmax[s][wn][row] = m_run[sl];
            g_psum[s][wn][row] = s_run[sl];
        }
    }
}

// ---------------- kernel: per-row NLL ----------------
__global__ void rownll_kernel() {
    int r = blockIdx.x * 256 + threadIdx.x;
    float m = g_pmax[0][0][r];
#pragma unroll
    for (int s = 0; s < NSPLIT; s++) {
        m = fmaxf(m, g_pmax[s][0][r]);
        m = fmaxf(m, g_pmax[s][1][r]);
    }
    float S = 0.f;
#pragma unroll
    for (int s = 0; s < NSPLIT; s++) {
        S += g_psum[s][0][r] * __expf(g_pmax[s][0][r] - m);
        S += g_psum[s][1][r] * __expf(g_pmax[s][1][r] - m);
    }
    g_row[r] = (m + logf(S)) - g_ll[r];
}

// ---------------- kernel: deterministic mean ----------------
__global__ void reduce_kernel(float* __restrict__ out) {
    __shared__ float red[256];
    int t = threadIdx.x;
    float local = 0.f;
#pragma unroll
    for (int i = 0; i < NROWS / 256; i++) local += g_row[t + i * 256];
    red[t] = local;
    __syncthreads();
    for (int off = 128; off; off >>= 1) {
        if (t < off) red[t] += red[t + off];
        __syncthreads();
    }
    if (t == 0) out[0] = red[0] * (1.0f / (float)NROWS);
}

// ---------------- launch (gemm kept 4th for ncu capture) ----------------
extern "C" void kernel_launch(void* const* d_in, const int* in_sizes, int n_in,
                              void* d_out, int out_size) {
    const int*   data  = (const int*)d_in[0];
    const int*   label = (const int*)d_in[1];
    const float* wte   = (const float*)d_in[2];
    const float* wpe   = (const float*)d_in[3];
    const float* W     = (const float*)d_in[4];
    float* out = (float*)d_out;

    cudaFuncSetAttribute(gemm_lse_kernel, cudaFuncAttributeMaxDynamicSharedMemorySize, SMEM_BYTES);

    prep_x_kernel<<<(NROWS * (NEMBD / 4)) / 256, 256>>>(data, wte, wpe);
    conv_w_kernel<<<(VPAD * (NEMBD / 4)) / 256, 256>>>(W);
    label_logit_kernel<<<NROWS / 8, 256>>>(label);
    gemm_lse_kernel<<<dim3(NSPLIT, NROWS / 64), 128, SMEM_BYTES>>>();
    rownll_kernel<<<NROWS / 256, 256>>>();
    reduce_kernel<<<1, 256>>>(out);
}